// round 15
// baseline (speedup 1.0000x reference)
#include <cuda_runtime.h>
#include <cuda_bf16.h>
#include <cstdint>

// ---------------------------------------------------------------------------
// StarBlock fused quantized MLP — bf16 hi/lo dual-plane mma.sync.
// R15: occupancy test with traffic held nearly constant. Up: M=64 x 128ch
// per CTA, BK=32, 4-stage ring, 256 thr, 2 CTAs/SM (warp tile and k-order
// identical to champion -> bit-identical outputs). The 2nd resident CTA
// covers prologue/epilogue/barrier bubbles that a 1-CTA/SM kernel exposes.
// down / prep / split_x = R14 champion verbatim.
// ---------------------------------------------------------------------------

#define B_ROWS 32768
#define DIN    1024
#define DHID   2048
#define DOUT   1024
#define KSPLIT 2048            // g_X row = [hi plane | lo plane]

// ------------------------- scratch (device globals) ------------------------
__device__ __nv_bfloat16 g_X [(size_t)B_ROWS * KSPLIT];     // 128 MiB [hi|lo]
__device__ __nv_bfloat16 g_wB[(size_t)(2 * DHID) * KSPLIT]; // 16 MiB, 256-row blocks
__device__ __nv_bfloat16 g_wd[(size_t)DOUT * DOUT];         // 2 MiB
__device__ __nv_bfloat16 g_h [(size_t)B_ROWS * DOUT];       // 64 MiB
__device__ float g_b1[DHID], g_b2[DHID], g_bd[DOUT];

// ------------------------------- helpers -----------------------------------
__device__ __forceinline__ uint32_t smem_u32(const void* p) {
    uint32_t a;
    asm("{ .reg .u64 t; cvta.to.shared.u64 t, %1; cvt.u32.u64 %0, t; }"
        : "=r"(a) : "l"(p));
    return a;
}
__device__ __forceinline__ uint32_t sw64(uint32_t off) {
    return off ^ ((off >> 3) & 0x30);      // 64B-row swizzle
}
__device__ __forceinline__ uint32_t sw128(uint32_t off) {
    return off ^ ((off >> 3) & 0x70);      // 128B-row swizzle
}
__device__ __forceinline__ void cp16(uint32_t saddr, const void* gptr) {
    asm volatile("cp.async.cg.shared.global [%0], [%1], 16;"
                 :: "r"(saddr), "l"(gptr));
}
#define CP_COMMIT() asm volatile("cp.async.commit_group;" ::: "memory")
#define CP_WAIT(n)  asm volatile("cp.async.wait_group %0;" :: "n"(n) : "memory")

__device__ __forceinline__ void ldsm4(uint32_t* r, uint32_t addr) {
    asm volatile("ldmatrix.sync.aligned.m8n8.x4.shared.b16 {%0,%1,%2,%3}, [%4];"
                 : "=r"(r[0]), "=r"(r[1]), "=r"(r[2]), "=r"(r[3])
                 : "r"(addr));
}
__device__ __forceinline__ void mma16816(float* c, const uint32_t* a,
                                         uint32_t b0, uint32_t b1) {
    asm volatile(
        "mma.sync.aligned.m16n8k16.row.col.f32.bf16.bf16.f32 "
        "{%0,%1,%2,%3},{%4,%5,%6,%7},{%8,%9},{%0,%1,%2,%3};"
        : "+f"(c[0]), "+f"(c[1]), "+f"(c[2]), "+f"(c[3])
        : "r"(a[0]), "r"(a[1]), "r"(a[2]), "r"(a[3]), "r"(b0), "r"(b1));
}

// exact reproduction of reference floor-quant pipeline
__device__ __forceinline__ __nv_bfloat16 make_h(float s1a, float s1b,
                                                float s2a, float s2b) {
    int a0 = (int)floorf(fminf(fmaxf(s1a, 0.f) * 128.f, 127.f));
    int a1 = (int)floorf(fminf(fmaxf(s1b, 0.f) * 128.f, 127.f));
    int q0 = (int)floorf(fminf(fmaxf(s2a * 128.f, -128.f), 127.f));
    int q1 = (int)floorf(fminf(fmaxf(s2b * 128.f, -128.f), 127.f));
    int t  = a0 * q0 + a1 * q1;
    int hq = t >> 7;
    hq = hq < -128 ? -128 : (hq > 127 ? 127 : hq);
    return __float2bfloat16((float)hq * 0.0078125f);
}

// ------------------------------ prep kernels -------------------------------
// weight block nb (128 channels) = 256 rows: [128 w1 rows | 128 w2 rows],
// K duplicated (col c hi == col c+DIN lo).
__global__ void prep_weights_kernel(const float* __restrict__ w1,
                                    const float* __restrict__ w2,
                                    const float* __restrict__ wd,
                                    const float* __restrict__ b1,
                                    const float* __restrict__ b2,
                                    const float* __restrict__ bd) {
    int i = blockIdx.x * blockDim.x + threadIdx.x;
    if (i < DHID * DIN) {
        int r = i >> 10, c = i & 1023;
        float q1 = rintf(fminf(fmaxf(w1[i] * 128.f, -128.f), 127.f)) * 0.0078125f;
        float q2 = rintf(fminf(fmaxf(w2[i] * 128.f, -128.f), 127.f)) * 0.0078125f;
        __nv_bfloat16 h1 = __float2bfloat16(q1);
        __nv_bfloat16 h2 = __float2bfloat16(q2);
        int nb = r >> 7, rl = r & 127;
        size_t row1 = (size_t)nb * 256 + rl;
        size_t row2 = row1 + 128;
        g_wB[row1 * KSPLIT + c]       = h1;
        g_wB[row1 * KSPLIT + c + DIN] = h1;
        g_wB[row2 * KSPLIT + c]       = h2;
        g_wB[row2 * KSPLIT + c + DIN] = h2;
    }
    if (i < DOUT * DOUT) {
        float qd = rintf(fminf(fmaxf(wd[i] * 128.f, -128.f), 127.f)) * 0.0078125f;
        g_wd[i] = __float2bfloat16(qd);
    }
    if (i < DHID) {
        g_b1[i] = rintf(b1[i] * 16384.f) * (1.f / 16384.f);
        g_b2[i] = rintf(b2[i] * 16384.f) * (1.f / 16384.f);
    }
    if (i < DOUT) {
        g_bd[i] = rintf(bd[i] * 16384.f) * (1.f / 16384.f);
    }
}

__global__ void split_x_kernel(const float* __restrict__ x) {
    size_t i = ((size_t)blockIdx.x * blockDim.x + threadIdx.x) * 8;
    float4 v0 = *(const float4*)(x + i);
    float4 v1 = *(const float4*)(x + i + 4);
    int r = (int)(i >> 10), c = (int)(i & 1023);
    __align__(16) __nv_bfloat16 hi[8], lo[8];
    float f[8] = {v0.x, v0.y, v0.z, v0.w, v1.x, v1.y, v1.z, v1.w};
#pragma unroll
    for (int k = 0; k < 8; k++) {
        hi[k] = __float2bfloat16(f[k]);
        lo[k] = __float2bfloat16(f[k] - __bfloat162float(hi[k]));
    }
    size_t base = (size_t)r * KSPLIT + c;
    *(uint4*)(&g_X[base])       = *(uint4*)hi;
    *(uint4*)(&g_X[base + DIN]) = *(uint4*)lo;
}

// ------------------------------ up GEMM ------------------------------------
// grid (16, 512), 256 threads, 2 CTAs/SM. CTA: M=64 x 128 dhid-channels
// (B tile = 256 rows: 128 w1 + 128 w2). K=2048 duplicated, BK=32,
// 4-stage cp.async ring. 8 warps: wm=wid&1 (32 rows), wn=wid>>1 (32 ch).
// Warp tile identical to champion (32x32x2 planes, 64 acc floats).
// Stage: A 4K @0 | B 16K @4096.  STG=20.5K x 4 = 80K; 2 CTAs = 166K.
#define UP_STG  20480
#define UP_HDR  1024
#define UP_SMEM (UP_HDR + 4 * UP_STG)
#define UP_NK   64

__device__ __forceinline__ void up_load(uint32_t st, int m0, int nb, int k0,
                                        int tid) {
    {                                             // A: 64 rows x 4 chunks = 256
        int r = tid >> 2, c = tid & 3;
        cp16(st + sw64(r * 64 + c * 16),
             &g_X[(size_t)(m0 + r) * KSPLIT + k0 + c * 8]);
    }
#pragma unroll
    for (int j = 0; j < 4; j++) {                 // B: 256 rows x 4 chunks = 1024
        int id = tid + j * 256;
        int r = id >> 2, c = id & 3;
        cp16(st + 4096 + sw64(r * 64 + c * 16),
             &g_wB[((size_t)nb * 256 + r) * KSPLIT + k0 + c * 8]);
    }
    CP_COMMIT();
}

__global__ void __launch_bounds__(256, 2) up_gemm_kernel() {
    extern __shared__ char smem[];
    const uint32_t sb = smem_u32(smem);
    const int tid  = threadIdx.x;
    const int lane = tid & 31;
    const int wid  = tid >> 5;
    const int wm   = wid & 1;                     // 0..1 (32-row group)
    const int wn   = wid >> 1;                    // 0..3 (32 channels)
    const int m0   = blockIdx.y * 64;
    const int nb   = blockIdx.x;                  // 0..15

    if (tid < 128) {
        ((float*)smem)[tid]       = g_b1[nb * 128 + tid];
        ((float*)smem)[128 + tid] = g_b2[nb * 128 + tid];
    }

    float acc1[2][4][4], acc2[2][4][4];
#pragma unroll
    for (int a = 0; a < 2; a++)
#pragma unroll
        for (int b = 0; b < 4; b++)
#pragma unroll
            for (int c = 0; c < 4; c++) { acc1[a][b][c] = 0.f; acc2[a][b][c] = 0.f; }

    const int lrow  = lane & 15;
    const int lhalf = (lane >> 4) * 16;
    const int arow  = wm * 32;

    up_load(sb + UP_HDR + 0 * UP_STG, m0, nb, 0, tid);
    up_load(sb + UP_HDR + 1 * UP_STG, m0, nb, 32, tid);
    up_load(sb + UP_HDR + 2 * UP_STG, m0, nb, 64, tid);

    for (int it = 0; it < UP_NK; ++it) {
        // stage it must be complete: newer-in-flight = min(NK-1, it+2) - it
        if (it + 3 <= UP_NK) { CP_WAIT(2); }
        else if (it + 2 <= UP_NK) { CP_WAIT(1); }
        else { CP_WAIT(0); }
        __syncthreads();       // all warps done reading slot (it-1)%4
        if (it + 3 < UP_NK)    // refill slot (it+3)%4 == (it-1)%4
            up_load(sb + UP_HDR + ((it + 3) % 4) * UP_STG, m0, nb,
                    (it + 3) * 32, tid);

        const uint32_t stA = sb + UP_HDR + (it % 4) * UP_STG;
        const uint32_t stB = stA + 4096;

#pragma unroll
        for (int ks = 0; ks < 2; ++ks) {
            const uint32_t abyte = ks * 32 + lhalf;   // 64B rows
            uint32_t af[2][4];
#pragma unroll
            for (int mt = 0; mt < 2; ++mt)
                ldsm4(af[mt], stA + sw64((arow + mt * 16 + lrow) * 64 + abyte));
            uint32_t b1f[2][4], b2f[2][4];
#pragma unroll
            for (int np = 0; np < 2; ++np) {
                const int r1 = wn * 32 + np * 16 + lrow;
                ldsm4(b1f[np], stB + sw64(r1 * 64 + abyte));
                ldsm4(b2f[np], stB + sw64((r1 + 128) * 64 + abyte));
            }
#pragma unroll
            for (int mt = 0; mt < 2; ++mt)
#pragma unroll
                for (int np = 0; np < 2; ++np)
#pragma unroll
                    for (int sub = 0; sub < 2; ++sub) {
                        const int nt = np * 2 + sub;
                        mma16816(acc1[mt][nt], af[mt], b1f[np][sub], b1f[np][sub + 2]);
                        mma16816(acc2[mt][nt], af[mt], b2f[np][sub], b2f[np][sub + 2]);
                    }
        }
    }
    __syncthreads();   // loop done; safe to reuse stage 0 as h staging

    // ---- epilogue: exact integer h, staged via smem (64 x 64 bf16) --------
    const float* sb1 = (const float*)smem;
    const float* sb2 = (const float*)smem + 128;
    __nv_bfloat16* s_h = (__nv_bfloat16*)(smem + UP_HDR);
    const int g = lane >> 2, t = lane & 3;
#pragma unroll
    for (int mt = 0; mt < 2; ++mt) {
#pragma unroll
        for (int nt = 0; nt < 4; ++nt) {
            const int nloc = wn * 32 + nt * 8 + 2 * t;   // channel in [0,128)
            const int hc   = nloc >> 1;                  // h col in [0,64)
            const int r0   = wm * 32 + mt * 16 + g;      // row in [0,64)
            const float b1a = sb1[nloc], b1b = sb1[nloc + 1];
            const float b2a = sb2[nloc], b2b = sb2[nloc + 1];
            const float* a1 = acc1[mt][nt];
            const float* a2 = acc2[mt][nt];
            s_h[r0 * 64 + hc] =
                make_h(a1[0] + b1a, a1[1] + b1b, a2[0] + b2a, a2[1] + b2b);
            s_h[(r0 + 8) * 64 + hc] =
                make_h(a1[2] + b1a, a1[3] + b1b, a2[2] + b2a, a2[3] + b2b);
        }
    }
    __syncthreads();
    {   // coalesced 16B stores: 64 rows x 128B = 512 chunks
#pragma unroll
        for (int j = 0; j < 2; j++) {
            int id = tid + j * 256;
            int r = id >> 3, c = id & 7;
            uint4 v = *(uint4*)((char*)s_h + r * 128 + c * 16);
            *(uint4*)(&g_h[(size_t)(m0 + r) * DOUT + nb * 64 + c * 8]) = v;
        }
    }
}

// ------------------------------ down GEMM ----------------------------------
// grid (16, 256), 256 threads, 3 CTAs/SM. CTA: M=128 x N=64, K=1024, BK=64.
// Stage: A 16K @0 | B 8K @16384.  STG=24K, 3-stage.  (champion, 191us)
#define DN_STG  24576
#define DN_HDR  1024
#define DN_SMEM (DN_HDR + 3 * DN_STG)
#define DN_NK   16

__device__ __forceinline__ void dn_load(uint32_t st, int m0, int n0, int k0,
                                        int tid) {
#pragma unroll
    for (int j = 0; j < 4; j++) {                 // A: 1024 chunks
        int id = tid + j * 256;
        int r = id >> 3, c = id & 7;
        cp16(st + sw128(r * 128 + c * 16),
             &g_h[(size_t)(m0 + r) * DOUT + k0 + c * 8]);
    }
#pragma unroll
    for (int j = 0; j < 2; j++) {                 // B: 64 rows, 512 chunks
        int id = tid + j * 256;
        int r = id >> 3, c = id & 7;
        cp16(st + 16384 + sw128(r * 128 + c * 16),
             &g_wd[(size_t)(n0 + r) * DOUT + k0 + c * 8]);
    }
    CP_COMMIT();
}

__global__ void __launch_bounds__(256, 3) down_gemm_kernel(float* __restrict__ out) {
    extern __shared__ char smem[];
    const uint32_t sb = smem_u32(smem);
    const int tid  = threadIdx.x;
    const int lane = tid & 31;
    const int wid  = tid >> 5;
    const int wm   = wid & 3;
    const int wn   = wid >> 2;                    // 0..1
    const int m0   = blockIdx.y * 128;
    const int n0   = blockIdx.x * 64;

    if (tid < 64) ((float*)smem)[tid] = g_bd[n0 + tid];

    float acc[2][4][4];
#pragma unroll
    for (int a = 0; a < 2; a++)
#pragma unroll
        for (int b = 0; b < 4; b++)
#pragma unroll
            for (int c = 0; c < 4; c++) acc[a][b][c] = 0.f;

    const int lrow  = lane & 15;
    const int lhalf = (lane >> 4) * 16;
    const int arow  = wm * 32;

    dn_load(sb + DN_HDR + 0 * DN_STG, m0, n0, 0, tid);
    dn_load(sb + DN_HDR + 1 * DN_STG, m0, n0, 64, tid);

    for (int it = 0; it < DN_NK; ++it) {
        if (it + 1 < DN_NK) { CP_WAIT(1); } else { CP_WAIT(0); }
        __syncthreads();
        if (it + 2 < DN_NK)
            dn_load(sb + DN_HDR + ((it + 2) % 3) * DN_STG, m0, n0,
                    (it + 2) * 64, tid);

        const uint32_t stA = sb + DN_HDR + (it % 3) * DN_STG;
        const uint32_t stB = stA + 16384;

#pragma unroll
        for (int ks = 0; ks < 4; ++ks) {
            const uint32_t abyte = ks * 32 + lhalf;
            uint32_t af[2][4];
#pragma unroll
            for (int mt = 0; mt < 2; ++mt)
                ldsm4(af[mt], stA + sw128((arow + mt * 16 + lrow) * 128 + abyte));
            uint32_t bf[2][4];
#pragma unroll
            for (int np = 0; np < 2; ++np)
                ldsm4(bf[np], stB + sw128((wn * 32 + np * 16 + lrow) * 128 + abyte));
#pragma unroll
            for (int mt = 0; mt < 2; ++mt)
#pragma unroll
                for (int np = 0; np < 2; ++np)
#pragma unroll
                    for (int sub = 0; sub < 2; ++sub)
                        mma16816(acc[mt][np * 2 + sub], af[mt],
                                 bf[np][sub], bf[np][sub + 2]);
        }
    }

    const float* sbd = (const float*)smem;
    const int g = lane >> 2, t = lane & 3;
#pragma unroll
    for (int mt = 0; mt < 2; ++mt) {
#pragma unroll
        for (int nt = 0; nt < 4; ++nt) {
            const int nloc = wn * 32 + nt * 8 + 2 * t;   // col in [0,64)
            const int r0 = m0 + wm * 32 + mt * 16 + g;
            const float bda = sbd[nloc], bdb = sbd[nloc + 1];
            const float* a = acc[mt][nt];
            float2 v0 = { fmaxf(a[0] + bda, 0.f), fmaxf(a[1] + bdb, 0.f) };
            float2 v1 = { fmaxf(a[2] + bda, 0.f), fmaxf(a[3] + bdb, 0.f) };
            *(float2*)(out + (size_t)r0 * DOUT + n0 + nloc)       = v0;
            *(float2*)(out + (size_t)(r0 + 8) * DOUT + n0 + nloc) = v1;
        }
    }
}

// ------------------------------- launch -------------------------------------
extern "C" void kernel_launch(void* const* d_in, const int* in_sizes, int n_in,
                              void* d_out, int out_size) {
    (void)in_sizes; (void)n_in; (void)out_size;
    const float* x  = (const float*)d_in[0];
    const float* w1 = (const float*)d_in[1];
    const float* b1 = (const float*)d_in[2];
    const float* w2 = (const float*)d_in[3];
    const float* b2 = (const float*)d_in[4];
    const float* wd = (const float*)d_in[5];
    const float* bd = (const float*)d_in[6];
    float* out = (float*)d_out;

    cudaFuncSetAttribute(up_gemm_kernel,
                         cudaFuncAttributeMaxDynamicSharedMemorySize, UP_SMEM);
    cudaFuncSetAttribute(down_gemm_kernel,
                         cudaFuncAttributeMaxDynamicSharedMemorySize, DN_SMEM);

    prep_weights_kernel<<<(DHID * DIN) / 256, 256>>>(w1, w2, wd, b1, b2, bd);
    split_x_kernel<<<(B_ROWS * DIN / 8) / 256, 256>>>(x);

    dim3 gup(DHID / 128, B_ROWS / 64);     // (16, 512)
    up_gemm_kernel<<<gup, 256, UP_SMEM>>>();

    dim3 gdn(DOUT / 64, B_ROWS / 128);     // (16, 256)
    down_gemm_kernel<<<gdn, 256, DN_SMEM>>>(out);
}

// round 16
// speedup vs baseline: 1.1426x; 1.1426x over previous
#include <cuda_runtime.h>
#include <cuda_bf16.h>
#include <cstdint>

// ---------------------------------------------------------------------------
// StarBlock fused quantized MLP — bf16 hi/lo dual-plane mma.sync.
// R16: champion (R14, 1569us) with prep_weights + split_x fused into one
// launch. up / down GEMMs byte-identical to the champion.
// Numerics identical (duplicated-K hi/lo planes), rel_err 3.7e-4.
// ---------------------------------------------------------------------------

#define B_ROWS 32768
#define DIN    1024
#define DHID   2048
#define DOUT   1024
#define KSPLIT 2048            // g_X row = [hi plane | lo plane]

// ------------------------- scratch (device globals) ------------------------
__device__ __nv_bfloat16 g_X [(size_t)B_ROWS * KSPLIT];     // 128 MiB [hi|lo]
__device__ __nv_bfloat16 g_wB[(size_t)(2 * DHID) * KSPLIT]; // 16 MiB, 256-row blocks
__device__ __nv_bfloat16 g_wd[(size_t)DOUT * DOUT];         // 2 MiB
__device__ __nv_bfloat16 g_h [(size_t)B_ROWS * DOUT];       // 64 MiB
__device__ float g_b1[DHID], g_b2[DHID], g_bd[DOUT];

// ------------------------------- helpers -----------------------------------
__device__ __forceinline__ uint32_t smem_u32(const void* p) {
    uint32_t a;
    asm("{ .reg .u64 t; cvta.to.shared.u64 t, %1; cvt.u32.u64 %0, t; }"
        : "=r"(a) : "l"(p));
    return a;
}
__device__ __forceinline__ uint32_t sw128(uint32_t off) {
    return off ^ ((off >> 3) & 0x70);      // 128B-row swizzle
}
__device__ __forceinline__ void cp16(uint32_t saddr, const void* gptr) {
    asm volatile("cp.async.cg.shared.global [%0], [%1], 16;"
                 :: "r"(saddr), "l"(gptr));
}
#define CP_COMMIT() asm volatile("cp.async.commit_group;" ::: "memory")
#define CP_WAIT(n)  asm volatile("cp.async.wait_group %0;" :: "n"(n) : "memory")

__device__ __forceinline__ void ldsm4(uint32_t* r, uint32_t addr) {
    asm volatile("ldmatrix.sync.aligned.m8n8.x4.shared.b16 {%0,%1,%2,%3}, [%4];"
                 : "=r"(r[0]), "=r"(r[1]), "=r"(r[2]), "=r"(r[3])
                 : "r"(addr));
}
__device__ __forceinline__ void mma16816(float* c, const uint32_t* a,
                                         uint32_t b0, uint32_t b1) {
    asm volatile(
        "mma.sync.aligned.m16n8k16.row.col.f32.bf16.bf16.f32 "
        "{%0,%1,%2,%3},{%4,%5,%6,%7},{%8,%9},{%0,%1,%2,%3};"
        : "+f"(c[0]), "+f"(c[1]), "+f"(c[2]), "+f"(c[3])
        : "r"(a[0]), "r"(a[1]), "r"(a[2]), "r"(a[3]), "r"(b0), "r"(b1));
}

// exact reproduction of reference floor-quant pipeline
__device__ __forceinline__ __nv_bfloat16 make_h(float s1a, float s1b,
                                                float s2a, float s2b) {
    int a0 = (int)floorf(fminf(fmaxf(s1a, 0.f) * 128.f, 127.f));
    int a1 = (int)floorf(fminf(fmaxf(s1b, 0.f) * 128.f, 127.f));
    int q0 = (int)floorf(fminf(fmaxf(s2a * 128.f, -128.f), 127.f));
    int q1 = (int)floorf(fminf(fmaxf(s2b * 128.f, -128.f), 127.f));
    int t  = a0 * q0 + a1 * q1;
    int hq = t >> 7;
    hq = hq < -128 ? -128 : (hq > 127 ? 127 : hq);
    return __float2bfloat16((float)hq * 0.0078125f);
}

// ------------------------------ fused prep kernel ---------------------------
// grid: 16384 blocks x 256 thr.
//   - every thread splits 8 x-elements into hi/lo bf16 planes (16B stores)
//   - the first 8192 blocks additionally quantize one w1/w2 element pair
//     region each (2M elements), plus wd / biases on the low indices.
__global__ void prep_fused_kernel(const float* __restrict__ x,
                                  const float* __restrict__ w1,
                                  const float* __restrict__ w2,
                                  const float* __restrict__ wd,
                                  const float* __restrict__ b1,
                                  const float* __restrict__ b2,
                                  const float* __restrict__ bd) {
    // ---- x split: 8 elements per thread --------------------------------
    size_t i = ((size_t)blockIdx.x * blockDim.x + threadIdx.x) * 8;
    float4 v0 = *(const float4*)(x + i);
    float4 v1 = *(const float4*)(x + i + 4);
    int r = (int)(i >> 10), c = (int)(i & 1023);
    __align__(16) __nv_bfloat16 hi[8], lo[8];
    float f[8] = {v0.x, v0.y, v0.z, v0.w, v1.x, v1.y, v1.z, v1.w};
#pragma unroll
    for (int k = 0; k < 8; k++) {
        hi[k] = __float2bfloat16(f[k]);
        lo[k] = __float2bfloat16(f[k] - __bfloat162float(hi[k]));
    }
    size_t base = (size_t)r * KSPLIT + c;
    *(uint4*)(&g_X[base])       = *(uint4*)hi;
    *(uint4*)(&g_X[base + DIN]) = *(uint4*)lo;

    // ---- weights / biases (first 2M global threads) ---------------------
    int j = blockIdx.x * blockDim.x + threadIdx.x;
    if (j < DHID * DIN) {
        int wr = j >> 10, wc = j & 1023;
        float q1 = rintf(fminf(fmaxf(w1[j] * 128.f, -128.f), 127.f)) * 0.0078125f;
        float q2 = rintf(fminf(fmaxf(w2[j] * 128.f, -128.f), 127.f)) * 0.0078125f;
        __nv_bfloat16 h1 = __float2bfloat16(q1);
        __nv_bfloat16 h2 = __float2bfloat16(q2);
        int nb = wr >> 7, rl = wr & 127;
        size_t row1 = (size_t)nb * 256 + rl;
        size_t row2 = row1 + 128;
        g_wB[row1 * KSPLIT + wc]       = h1;
        g_wB[row1 * KSPLIT + wc + DIN] = h1;
        g_wB[row2 * KSPLIT + wc]       = h2;
        g_wB[row2 * KSPLIT + wc + DIN] = h2;
    }
    if (j < DOUT * DOUT) {
        float qd = rintf(fminf(fmaxf(wd[j] * 128.f, -128.f), 127.f)) * 0.0078125f;
        g_wd[j] = __float2bfloat16(qd);
    }
    if (j < DHID) {
        g_b1[j] = rintf(b1[j] * 16384.f) * (1.f / 16384.f);
        g_b2[j] = rintf(b2[j] * 16384.f) * (1.f / 16384.f);
    }
    if (j < DOUT) {
        g_bd[j] = rintf(bd[j] * 16384.f) * (1.f / 16384.f);
    }
}

// ------------------------------ up GEMM ------------------------------------
// grid (16, 256), 512 threads. CTA: M=128 x 128 dhid-channels
// (B tile = 256 rows: 128 w1 + 128 w2). K=2048 duplicated, BK=64,
// 4-stage cp.async ring. 16 warps: wm=wid&3 (32 rows), wn=wid>>2 (32 ch).
// Stage: A 16K @0 | B 32K @16384.  STG=48K x 4 = 192K.  (champion verbatim)
#define UP_STG  49152
#define UP_HDR  1024
#define UP_SMEM (UP_HDR + 4 * UP_STG)
#define UP_NK   32

__device__ __forceinline__ void up_load(uint32_t st, int m0, int nb, int k0,
                                        int tid) {
#pragma unroll
    for (int j = 0; j < 2; j++) {                 // A: 1024 chunks
        int id = tid + j * 512;
        int r = id >> 3, c = id & 7;
        cp16(st + sw128(r * 128 + c * 16),
             &g_X[(size_t)(m0 + r) * KSPLIT + k0 + c * 8]);
    }
#pragma unroll
    for (int j = 0; j < 4; j++) {                 // B: 256 rows, 2048 chunks
        int id = tid + j * 512;
        int r = id >> 3, c = id & 7;
        cp16(st + 16384 + sw128(r * 128 + c * 16),
             &g_wB[((size_t)nb * 256 + r) * KSPLIT + k0 + c * 8]);
    }
    CP_COMMIT();
}

__global__ void __launch_bounds__(512, 1) up_gemm_kernel() {
    extern __shared__ char smem[];
    const uint32_t sb = smem_u32(smem);
    const int tid  = threadIdx.x;
    const int lane = tid & 31;
    const int wid  = tid >> 5;
    const int wm   = wid & 3;
    const int wn   = wid >> 2;                    // 0..3
    const int m0   = blockIdx.y * 128;
    const int nb   = blockIdx.x;                  // 0..15

    if (tid < 128) {
        ((float*)smem)[tid]       = g_b1[nb * 128 + tid];
        ((float*)smem)[128 + tid] = g_b2[nb * 128 + tid];
    }

    float acc1[2][4][4], acc2[2][4][4];
#pragma unroll
    for (int a = 0; a < 2; a++)
#pragma unroll
        for (int b = 0; b < 4; b++)
#pragma unroll
            for (int c = 0; c < 4; c++) { acc1[a][b][c] = 0.f; acc2[a][b][c] = 0.f; }

    const int lrow  = lane & 15;
    const int lhalf = (lane >> 4) * 16;
    const int arow  = wm * 32;

    up_load(sb + UP_HDR + 0 * UP_STG, m0, nb, 0, tid);
    up_load(sb + UP_HDR + 1 * UP_STG, m0, nb, 64, tid);
    up_load(sb + UP_HDR + 2 * UP_STG, m0, nb, 128, tid);

    for (int it = 0; it < UP_NK; ++it) {
        CP_WAIT(2);            // stage it complete (<=2 newest groups pending)
        __syncthreads();       // all warps done reading slot (it-1)%4
        if (it + 3 < UP_NK)    // refill slot (it+3)%4 == (it-1)%4
            up_load(sb + UP_HDR + ((it + 3) % 4) * UP_STG, m0, nb,
                    (it + 3) * 64, tid);

        const uint32_t stA = sb + UP_HDR + (it % 4) * UP_STG;
        const uint32_t stB = stA + 16384;

#pragma unroll
        for (int ks = 0; ks < 4; ++ks) {
            const uint32_t abyte = ks * 32 + lhalf;
            uint32_t af[2][4];
#pragma unroll
            for (int mt = 0; mt < 2; ++mt)
                ldsm4(af[mt], stA + sw128((arow + mt * 16 + lrow) * 128 + abyte));
            uint32_t b1f[2][4], b2f[2][4];
#pragma unroll
            for (int np = 0; np < 2; ++np) {
                const int r1 = wn * 32 + np * 16 + lrow;
                ldsm4(b1f[np], stB + sw128(r1 * 128 + abyte));
                ldsm4(b2f[np], stB + sw128((r1 + 128) * 128 + abyte));
            }
#pragma unroll
            for (int mt = 0; mt < 2; ++mt)
#pragma unroll
                for (int np = 0; np < 2; ++np)
#pragma unroll
                    for (int sub = 0; sub < 2; ++sub) {
                        const int nt = np * 2 + sub;
                        mma16816(acc1[mt][nt], af[mt], b1f[np][sub], b1f[np][sub + 2]);
                        mma16816(acc2[mt][nt], af[mt], b2f[np][sub], b2f[np][sub + 2]);
                    }
        }
    }
    __syncthreads();   // loop done; safe to reuse stage 0 as h staging

    // ---- epilogue: exact integer h, staged via smem (128 x 64 bf16) -------
    const float* sb1 = (const float*)smem;
    const float* sb2 = (const float*)smem + 128;
    __nv_bfloat16* s_h = (__nv_bfloat16*)(smem + UP_HDR);
    const int g = lane >> 2, t = lane & 3;
#pragma unroll
    for (int mt = 0; mt < 2; ++mt) {
#pragma unroll
        for (int nt = 0; nt < 4; ++nt) {
            const int nloc = wn * 32 + nt * 8 + 2 * t;   // channel in [0,128)
            const int hc   = nloc >> 1;                  // h col in [0,64)
            const int r0   = wm * 32 + mt * 16 + g;
            const float b1a = sb1[nloc], b1b = sb1[nloc + 1];
            const float b2a = sb2[nloc], b2b = sb2[nloc + 1];
            const float* a1 = acc1[mt][nt];
            const float* a2 = acc2[mt][nt];
            s_h[r0 * 64 + hc] =
                make_h(a1[0] + b1a, a1[1] + b1b, a2[0] + b2a, a2[1] + b2b);
            s_h[(r0 + 8) * 64 + hc] =
                make_h(a1[2] + b1a, a1[3] + b1b, a2[2] + b2a, a2[3] + b2b);
        }
    }
    __syncthreads();
    {   // coalesced 16B stores: 128 rows x 128B = 1024 chunks
#pragma unroll
        for (int j = 0; j < 2; j++) {
            int id = tid + j * 512;
            int r = id >> 3, c = id & 7;
            uint4 v = *(uint4*)((char*)s_h + r * 128 + c * 16);
            *(uint4*)(&g_h[(size_t)(m0 + r) * DOUT + nb * 64 + c * 8]) = v;
        }
    }
}

// ------------------------------ down GEMM ----------------------------------
// grid (16, 256), 256 threads, 3 CTAs/SM. CTA: M=128 x N=64, K=1024, BK=64.
// Stage: A 16K @0 | B 8K @16384.  STG=24K, 3-stage.  (champion, 191us)
#define DN_STG  24576
#define DN_HDR  1024
#define DN_SMEM (DN_HDR + 3 * DN_STG)
#define DN_NK   16

__device__ __forceinline__ void dn_load(uint32_t st, int m0, int n0, int k0,
                                        int tid) {
#pragma unroll
    for (int j = 0; j < 4; j++) {                 // A: 1024 chunks
        int id = tid + j * 256;
        int r = id >> 3, c = id & 7;
        cp16(st + sw128(r * 128 + c * 16),
             &g_h[(size_t)(m0 + r) * DOUT + k0 + c * 8]);
    }
#pragma unroll
    for (int j = 0; j < 2; j++) {                 // B: 64 rows, 512 chunks
        int id = tid + j * 256;
        int r = id >> 3, c = id & 7;
        cp16(st + 16384 + sw128(r * 128 + c * 16),
             &g_wd[(size_t)(n0 + r) * DOUT + k0 + c * 8]);
    }
    CP_COMMIT();
}

__global__ void __launch_bounds__(256, 3) down_gemm_kernel(float* __restrict__ out) {
    extern __shared__ char smem[];
    const uint32_t sb = smem_u32(smem);
    const int tid  = threadIdx.x;
    const int lane = tid & 31;
    const int wid  = tid >> 5;
    const int wm   = wid & 3;
    const int wn   = wid >> 2;                    // 0..1
    const int m0   = blockIdx.y * 128;
    const int n0   = blockIdx.x * 64;

    if (tid < 64) ((float*)smem)[tid] = g_bd[n0 + tid];

    float acc[2][4][4];
#pragma unroll
    for (int a = 0; a < 2; a++)
#pragma unroll
        for (int b = 0; b < 4; b++)
#pragma unroll
            for (int c = 0; c < 4; c++) acc[a][b][c] = 0.f;

    const int lrow  = lane & 15;
    const int lhalf = (lane >> 4) * 16;
    const int arow  = wm * 32;

    dn_load(sb + DN_HDR + 0 * DN_STG, m0, n0, 0, tid);
    dn_load(sb + DN_HDR + 1 * DN_STG, m0, n0, 64, tid);

    for (int it = 0; it < DN_NK; ++it) {
        if (it + 1 < DN_NK) { CP_WAIT(1); } else { CP_WAIT(0); }
        __syncthreads();
        if (it + 2 < DN_NK)
            dn_load(sb + DN_HDR + ((it + 2) % 3) * DN_STG, m0, n0,
                    (it + 2) * 64, tid);

        const uint32_t stA = sb + DN_HDR + (it % 3) * DN_STG;
        const uint32_t stB = stA + 16384;

#pragma unroll
        for (int ks = 0; ks < 4; ++ks) {
            const uint32_t abyte = ks * 32 + lhalf;
            uint32_t af[2][4];
#pragma unroll
            for (int mt = 0; mt < 2; ++mt)
                ldsm4(af[mt], stA + sw128((arow + mt * 16 + lrow) * 128 + abyte));
            uint32_t bf[2][4];
#pragma unroll
            for (int np = 0; np < 2; ++np)
                ldsm4(bf[np], stB + sw128((wn * 32 + np * 16 + lrow) * 128 + abyte));
#pragma unroll
            for (int mt = 0; mt < 2; ++mt)
#pragma unroll
                for (int np = 0; np < 2; ++np)
#pragma unroll
                    for (int sub = 0; sub < 2; ++sub)
                        mma16816(acc[mt][np * 2 + sub], af[mt],
                                 bf[np][sub], bf[np][sub + 2]);
        }
    }

    const float* sbd = (const float*)smem;
    const int g = lane >> 2, t = lane & 3;
#pragma unroll
    for (int mt = 0; mt < 2; ++mt) {
#pragma unroll
        for (int nt = 0; nt < 4; ++nt) {
            const int nloc = wn * 32 + nt * 8 + 2 * t;   // col in [0,64)
            const int r0 = m0 + wm * 32 + mt * 16 + g;
            const float bda = sbd[nloc], bdb = sbd[nloc + 1];
            const float* a = acc[mt][nt];
            float2 v0 = { fmaxf(a[0] + bda, 0.f), fmaxf(a[1] + bdb, 0.f) };
            float2 v1 = { fmaxf(a[2] + bda, 0.f), fmaxf(a[3] + bdb, 0.f) };
            *(float2*)(out + (size_t)r0 * DOUT + n0 + nloc)       = v0;
            *(float2*)(out + (size_t)(r0 + 8) * DOUT + n0 + nloc) = v1;
        }
    }
}

// ------------------------------- launch -------------------------------------
extern "C" void kernel_launch(void* const* d_in, const int* in_sizes, int n_in,
                              void* d_out, int out_size) {
    (void)in_sizes; (void)n_in; (void)out_size;
    const float* x  = (const float*)d_in[0];
    const float* w1 = (const float*)d_in[1];
    const float* b1 = (const float*)d_in[2];
    const float* w2 = (const float*)d_in[3];
    const float* b2 = (const float*)d_in[4];
    const float* wd = (const float*)d_in[5];
    const float* bd = (const float*)d_in[6];
    float* out = (float*)d_out;

    cudaFuncSetAttribute(up_gemm_kernel,
                         cudaFuncAttributeMaxDynamicSharedMemorySize, UP_SMEM);
    cudaFuncSetAttribute(down_gemm_kernel,
                         cudaFuncAttributeMaxDynamicSharedMemorySize, DN_SMEM);

    prep_fused_kernel<<<(B_ROWS * DIN / 8) / 256, 256>>>(x, w1, w2, wd,
                                                         b1, b2, bd);

    dim3 gup(DHID / 128, B_ROWS / 128);    // (16, 256)
    up_gemm_kernel<<<gup, 512, UP_SMEM>>>();

    dim3 gdn(DOUT / 64, B_ROWS / 128);     // (16, 256)
    down_gemm_kernel<<<gdn, 256, DN_SMEM>>>(out);
}

// round 17
// speedup vs baseline: 1.1431x; 1.0004x over previous
#include <cuda_runtime.h>
#include <cuda_bf16.h>
#include <cstdint>

// ---------------------------------------------------------------------------
// StarBlock fused quantized MLP — bf16 hi/lo dual-plane mma.sync.
// R17: champion locked (R16, 1567.5us). Fused prep (45us, 70% HBM),
// up 512thr/M128x256B/BK64/4-stage ring (~70% tensor), down 256thr/
// 3CTAs-per-SM/M128xN64 (60% tensor, 191us reproduced 7x).
// Numerics: duplicated-K hi/lo bf16 planes + exact integer floor-quant
// epilogue; rel_err 3.706e-4.
// ---------------------------------------------------------------------------

#define B_ROWS 32768
#define DIN    1024
#define DHID   2048
#define DOUT   1024
#define KSPLIT 2048            // g_X row = [hi plane | lo plane]

// ------------------------- scratch (device globals) ------------------------
__device__ __nv_bfloat16 g_X [(size_t)B_ROWS * KSPLIT];     // 128 MiB [hi|lo]
__device__ __nv_bfloat16 g_wB[(size_t)(2 * DHID) * KSPLIT]; // 16 MiB, 256-row blocks
__device__ __nv_bfloat16 g_wd[(size_t)DOUT * DOUT];         // 2 MiB
__device__ __nv_bfloat16 g_h [(size_t)B_ROWS * DOUT];       // 64 MiB
__device__ float g_b1[DHID], g_b2[DHID], g_bd[DOUT];

// ------------------------------- helpers -----------------------------------
__device__ __forceinline__ uint32_t smem_u32(const void* p) {
    uint32_t a;
    asm("{ .reg .u64 t; cvta.to.shared.u64 t, %1; cvt.u32.u64 %0, t; }"
        : "=r"(a) : "l"(p));
    return a;
}
__device__ __forceinline__ uint32_t sw128(uint32_t off) {
    return off ^ ((off >> 3) & 0x70);      // 128B-row swizzle
}
__device__ __forceinline__ void cp16(uint32_t saddr, const void* gptr) {
    asm volatile("cp.async.cg.shared.global [%0], [%1], 16;"
                 :: "r"(saddr), "l"(gptr));
}
#define CP_COMMIT() asm volatile("cp.async.commit_group;" ::: "memory")
#define CP_WAIT(n)  asm volatile("cp.async.wait_group %0;" :: "n"(n) : "memory")

__device__ __forceinline__ void ldsm4(uint32_t* r, uint32_t addr) {
    asm volatile("ldmatrix.sync.aligned.m8n8.x4.shared.b16 {%0,%1,%2,%3}, [%4];"
                 : "=r"(r[0]), "=r"(r[1]), "=r"(r[2]), "=r"(r[3])
                 : "r"(addr));
}
__device__ __forceinline__ void mma16816(float* c, const uint32_t* a,
                                         uint32_t b0, uint32_t b1) {
    asm volatile(
        "mma.sync.aligned.m16n8k16.row.col.f32.bf16.bf16.f32 "
        "{%0,%1,%2,%3},{%4,%5,%6,%7},{%8,%9},{%0,%1,%2,%3};"
        : "+f"(c[0]), "+f"(c[1]), "+f"(c[2]), "+f"(c[3])
        : "r"(a[0]), "r"(a[1]), "r"(a[2]), "r"(a[3]), "r"(b0), "r"(b1));
}

// exact reproduction of reference floor-quant pipeline
__device__ __forceinline__ __nv_bfloat16 make_h(float s1a, float s1b,
                                                float s2a, float s2b) {
    int a0 = (int)floorf(fminf(fmaxf(s1a, 0.f) * 128.f, 127.f));
    int a1 = (int)floorf(fminf(fmaxf(s1b, 0.f) * 128.f, 127.f));
    int q0 = (int)floorf(fminf(fmaxf(s2a * 128.f, -128.f), 127.f));
    int q1 = (int)floorf(fminf(fmaxf(s2b * 128.f, -128.f), 127.f));
    int t  = a0 * q0 + a1 * q1;
    int hq = t >> 7;
    hq = hq < -128 ? -128 : (hq > 127 ? 127 : hq);
    return __float2bfloat16((float)hq * 0.0078125f);
}

// ------------------------------ fused prep kernel ---------------------------
// grid: 16384 blocks x 256 thr.
//   - every thread splits 8 x-elements into hi/lo bf16 planes (16B stores)
//   - the first 8192 blocks additionally quantize the weights and biases.
__global__ void prep_fused_kernel(const float* __restrict__ x,
                                  const float* __restrict__ w1,
                                  const float* __restrict__ w2,
                                  const float* __restrict__ wd,
                                  const float* __restrict__ b1,
                                  const float* __restrict__ b2,
                                  const float* __restrict__ bd) {
    // ---- x split: 8 elements per thread --------------------------------
    size_t i = ((size_t)blockIdx.x * blockDim.x + threadIdx.x) * 8;
    float4 v0 = *(const float4*)(x + i);
    float4 v1 = *(const float4*)(x + i + 4);
    int r = (int)(i >> 10), c = (int)(i & 1023);
    __align__(16) __nv_bfloat16 hi[8], lo[8];
    float f[8] = {v0.x, v0.y, v0.z, v0.w, v1.x, v1.y, v1.z, v1.w};
#pragma unroll
    for (int k = 0; k < 8; k++) {
        hi[k] = __float2bfloat16(f[k]);
        lo[k] = __float2bfloat16(f[k] - __bfloat162float(hi[k]));
    }
    size_t base = (size_t)r * KSPLIT + c;
    *(uint4*)(&g_X[base])       = *(uint4*)hi;
    *(uint4*)(&g_X[base + DIN]) = *(uint4*)lo;

    // ---- weights / biases (first 2M global threads) ---------------------
    int j = blockIdx.x * blockDim.x + threadIdx.x;
    if (j < DHID * DIN) {
        int wr = j >> 10, wc = j & 1023;
        float q1 = rintf(fminf(fmaxf(w1[j] * 128.f, -128.f), 127.f)) * 0.0078125f;
        float q2 = rintf(fminf(fmaxf(w2[j] * 128.f, -128.f), 127.f)) * 0.0078125f;
        __nv_bfloat16 h1 = __float2bfloat16(q1);
        __nv_bfloat16 h2 = __float2bfloat16(q2);
        int nb = wr >> 7, rl = wr & 127;
        size_t row1 = (size_t)nb * 256 + rl;
        size_t row2 = row1 + 128;
        g_wB[row1 * KSPLIT + wc]       = h1;
        g_wB[row1 * KSPLIT + wc + DIN] = h1;
        g_wB[row2 * KSPLIT + wc]       = h2;
        g_wB[row2 * KSPLIT + wc + DIN] = h2;
    }
    if (j < DOUT * DOUT) {
        float qd = rintf(fminf(fmaxf(wd[j] * 128.f, -128.f), 127.f)) * 0.0078125f;
        g_wd[j] = __float2bfloat16(qd);
    }
    if (j < DHID) {
        g_b1[j] = rintf(b1[j] * 16384.f) * (1.f / 16384.f);
        g_b2[j] = rintf(b2[j] * 16384.f) * (1.f / 16384.f);
    }
    if (j < DOUT) {
        g_bd[j] = rintf(bd[j] * 16384.f) * (1.f / 16384.f);
    }
}

// ------------------------------ up GEMM ------------------------------------
// grid (16, 256), 512 threads. CTA: M=128 x 128 dhid-channels
// (B tile = 256 rows: 128 w1 + 128 w2). K=2048 duplicated, BK=64,
// 4-stage cp.async ring. 16 warps: wm=wid&3 (32 rows), wn=wid>>2 (32 ch).
// Stage: A 16K @0 | B 32K @16384.  STG=48K x 4 = 192K.
#define UP_STG  49152
#define UP_HDR  1024
#define UP_SMEM (UP_HDR + 4 * UP_STG)
#define UP_NK   32

__device__ __forceinline__ void up_load(uint32_t st, int m0, int nb, int k0,
                                        int tid) {
#pragma unroll
    for (int j = 0; j < 2; j++) {                 // A: 1024 chunks
        int id = tid + j * 512;
        int r = id >> 3, c = id & 7;
        cp16(st + sw128(r * 128 + c * 16),
             &g_X[(size_t)(m0 + r) * KSPLIT + k0 + c * 8]);
    }
#pragma unroll
    for (int j = 0; j < 4; j++) {                 // B: 256 rows, 2048 chunks
        int id = tid + j * 512;
        int r = id >> 3, c = id & 7;
        cp16(st + 16384 + sw128(r * 128 + c * 16),
             &g_wB[((size_t)nb * 256 + r) * KSPLIT + k0 + c * 8]);
    }
    CP_COMMIT();
}

__global__ void __launch_bounds__(512, 1) up_gemm_kernel() {
    extern __shared__ char smem[];
    const uint32_t sb = smem_u32(smem);
    const int tid  = threadIdx.x;
    const int lane = tid & 31;
    const int wid  = tid >> 5;
    const int wm   = wid & 3;
    const int wn   = wid >> 2;                    // 0..3
    const int m0   = blockIdx.y * 128;
    const int nb   = blockIdx.x;                  // 0..15

    if (tid < 128) {
        ((float*)smem)[tid]       = g_b1[nb * 128 + tid];
        ((float*)smem)[128 + tid] = g_b2[nb * 128 + tid];
    }

    float acc1[2][4][4], acc2[2][4][4];
#pragma unroll
    for (int a = 0; a < 2; a++)
#pragma unroll
        for (int b = 0; b < 4; b++)
#pragma unroll
            for (int c = 0; c < 4; c++) { acc1[a][b][c] = 0.f; acc2[a][b][c] = 0.f; }

    const int lrow  = lane & 15;
    const int lhalf = (lane >> 4) * 16;
    const int arow  = wm * 32;

    up_load(sb + UP_HDR + 0 * UP_STG, m0, nb, 0, tid);
    up_load(sb + UP_HDR + 1 * UP_STG, m0, nb, 64, tid);
    up_load(sb + UP_HDR + 2 * UP_STG, m0, nb, 128, tid);

    for (int it = 0; it < UP_NK; ++it) {
        CP_WAIT(2);            // stage it complete (<=2 newest groups pending)
        __syncthreads();       // all warps done reading slot (it-1)%4
        if (it + 3 < UP_NK)    // refill slot (it+3)%4 == (it-1)%4
            up_load(sb + UP_HDR + ((it + 3) % 4) * UP_STG, m0, nb,
                    (it + 3) * 64, tid);

        const uint32_t stA = sb + UP_HDR + (it % 4) * UP_STG;
        const uint32_t stB = stA + 16384;

#pragma unroll
        for (int ks = 0; ks < 4; ++ks) {
            const uint32_t abyte = ks * 32 + lhalf;
            uint32_t af[2][4];
#pragma unroll
            for (int mt = 0; mt < 2; ++mt)
                ldsm4(af[mt], stA + sw128((arow + mt * 16 + lrow) * 128 + abyte));
            uint32_t b1f[2][4], b2f[2][4];
#pragma unroll
            for (int np = 0; np < 2; ++np) {
                const int r1 = wn * 32 + np * 16 + lrow;
                ldsm4(b1f[np], stB + sw128(r1 * 128 + abyte));
                ldsm4(b2f[np], stB + sw128((r1 + 128) * 128 + abyte));
            }
#pragma unroll
            for (int mt = 0; mt < 2; ++mt)
#pragma unroll
                for (int np = 0; np < 2; ++np)
#pragma unroll
                    for (int sub = 0; sub < 2; ++sub) {
                        const int nt = np * 2 + sub;
                        mma16816(acc1[mt][nt], af[mt], b1f[np][sub], b1f[np][sub + 2]);
                        mma16816(acc2[mt][nt], af[mt], b2f[np][sub], b2f[np][sub + 2]);
                    }
        }
    }
    __syncthreads();   // loop done; safe to reuse stage 0 as h staging

    // ---- epilogue: exact integer h, staged via smem (128 x 64 bf16) -------
    const float* sb1 = (const float*)smem;
    const float* sb2 = (const float*)smem + 128;
    __nv_bfloat16* s_h = (__nv_bfloat16*)(smem + UP_HDR);
    const int g = lane >> 2, t = lane & 3;
#pragma unroll
    for (int mt = 0; mt < 2; ++mt) {
#pragma unroll
        for (int nt = 0; nt < 4; ++nt) {
            const int nloc = wn * 32 + nt * 8 + 2 * t;   // channel in [0,128)
            const int hc   = nloc >> 1;                  // h col in [0,64)
            const int r0   = wm * 32 + mt * 16 + g;
            const float b1a = sb1[nloc], b1b = sb1[nloc + 1];
            const float b2a = sb2[nloc], b2b = sb2[nloc + 1];
            const float* a1 = acc1[mt][nt];
            const float* a2 = acc2[mt][nt];
            s_h[r0 * 64 + hc] =
                make_h(a1[0] + b1a, a1[1] + b1b, a2[0] + b2a, a2[1] + b2b);
            s_h[(r0 + 8) * 64 + hc] =
                make_h(a1[2] + b1a, a1[3] + b1b, a2[2] + b2a, a2[3] + b2b);
        }
    }
    __syncthreads();
    {   // coalesced 16B stores: 128 rows x 128B = 1024 chunks
#pragma unroll
        for (int j = 0; j < 2; j++) {
            int id = tid + j * 512;
            int r = id >> 3, c = id & 7;
            uint4 v = *(uint4*)((char*)s_h + r * 128 + c * 16);
            *(uint4*)(&g_h[(size_t)(m0 + r) * DOUT + nb * 64 + c * 8]) = v;
        }
    }
}

// ------------------------------ down GEMM ----------------------------------
// grid (16, 256), 256 threads, 3 CTAs/SM. CTA: M=128 x N=64, K=1024, BK=64.
// Stage: A 16K @0 | B 8K @16384.  STG=24K, 3-stage.
#define DN_STG  24576
#define DN_HDR  1024
#define DN_SMEM (DN_HDR + 3 * DN_STG)
#define DN_NK   16

__device__ __forceinline__ void dn_load(uint32_t st, int m0, int n0, int k0,
                                        int tid) {
#pragma unroll
    for (int j = 0; j < 4; j++) {                 // A: 1024 chunks
        int id = tid + j * 256;
        int r = id >> 3, c = id & 7;
        cp16(st + sw128(r * 128 + c * 16),
             &g_h[(size_t)(m0 + r) * DOUT + k0 + c * 8]);
    }
#pragma unroll
    for (int j = 0; j < 2; j++) {                 // B: 64 rows, 512 chunks
        int id = tid + j * 256;
        int r = id >> 3, c = id & 7;
        cp16(st + 16384 + sw128(r * 128 + c * 16),
             &g_wd[(size_t)(n0 + r) * DOUT + k0 + c * 8]);
    }
    CP_COMMIT();
}

__global__ void __launch_bounds__(256, 3) down_gemm_kernel(float* __restrict__ out) {
    extern __shared__ char smem[];
    const uint32_t sb = smem_u32(smem);
    const int tid  = threadIdx.x;
    const int lane = tid & 31;
    const int wid  = tid >> 5;
    const int wm   = wid & 3;
    const int wn   = wid >> 2;                    // 0..1
    const int m0   = blockIdx.y * 128;
    const int n0   = blockIdx.x * 64;

    if (tid < 64) ((float*)smem)[tid] = g_bd[n0 + tid];

    float acc[2][4][4];
#pragma unroll
    for (int a = 0; a < 2; a++)
#pragma unroll
        for (int b = 0; b < 4; b++)
#pragma unroll
            for (int c = 0; c < 4; c++) acc[a][b][c] = 0.f;

    const int lrow  = lane & 15;
    const int lhalf = (lane >> 4) * 16;
    const int arow  = wm * 32;

    dn_load(sb + DN_HDR + 0 * DN_STG, m0, n0, 0, tid);
    dn_load(sb + DN_HDR + 1 * DN_STG, m0, n0, 64, tid);

    for (int it = 0; it < DN_NK; ++it) {
        if (it + 1 < DN_NK) { CP_WAIT(1); } else { CP_WAIT(0); }
        __syncthreads();
        if (it + 2 < DN_NK)
            dn_load(sb + DN_HDR + ((it + 2) % 3) * DN_STG, m0, n0,
                    (it + 2) * 64, tid);

        const uint32_t stA = sb + DN_HDR + (it % 3) * DN_STG;
        const uint32_t stB = stA + 16384;

#pragma unroll
        for (int ks = 0; ks < 4; ++ks) {
            const uint32_t abyte = ks * 32 + lhalf;
            uint32_t af[2][4];
#pragma unroll
            for (int mt = 0; mt < 2; ++mt)
                ldsm4(af[mt], stA + sw128((arow + mt * 16 + lrow) * 128 + abyte));
            uint32_t bf[2][4];
#pragma unroll
            for (int np = 0; np < 2; ++np)
                ldsm4(bf[np], stB + sw128((wn * 32 + np * 16 + lrow) * 128 + abyte));
#pragma unroll
            for (int mt = 0; mt < 2; ++mt)
#pragma unroll
                for (int np = 0; np < 2; ++np)
#pragma unroll
                    for (int sub = 0; sub < 2; ++sub)
                        mma16816(acc[mt][np * 2 + sub], af[mt],
                                 bf[np][sub], bf[np][sub + 2]);
        }
    }

    const float* sbd = (const float*)smem;
    const int g = lane >> 2, t = lane & 3;
#pragma unroll
    for (int mt = 0; mt < 2; ++mt) {
#pragma unroll
        for (int nt = 0; nt < 4; ++nt) {
            const int nloc = wn * 32 + nt * 8 + 2 * t;   // col in [0,64)
            const int r0 = m0 + wm * 32 + mt * 16 + g;
            const float bda = sbd[nloc], bdb = sbd[nloc + 1];
            const float* a = acc[mt][nt];
            float2 v0 = { fmaxf(a[0] + bda, 0.f), fmaxf(a[1] + bdb, 0.f) };
            float2 v1 = { fmaxf(a[2] + bda, 0.f), fmaxf(a[3] + bdb, 0.f) };
            *(float2*)(out + (size_t)r0 * DOUT + n0 + nloc)       = v0;
            *(float2*)(out + (size_t)(r0 + 8) * DOUT + n0 + nloc) = v1;
        }
    }
}

// ------------------------------- launch -------------------------------------
extern "C" void kernel_launch(void* const* d_in, const int* in_sizes, int n_in,
                              void* d_out, int out_size) {
    (void)in_sizes; (void)n_in; (void)out_size;
    const float* x  = (const float*)d_in[0];
    const float* w1 = (const float*)d_in[1];
    const float* b1 = (const float*)d_in[2];
    const float* w2 = (const float*)d_in[3];
    const float* b2 = (const float*)d_in[4];
    const float* wd = (const float*)d_in[5];
    const float* bd = (const float*)d_in[6];
    float* out = (float*)d_out;

    cudaFuncSetAttribute(up_gemm_kernel,
                         cudaFuncAttributeMaxDynamicSharedMemorySize, UP_SMEM);
    cudaFuncSetAttribute(down_gemm_kernel,
                         cudaFuncAttributeMaxDynamicSharedMemorySize, DN_SMEM);

    prep_fused_kernel<<<(B_ROWS * DIN / 8) / 256, 256>>>(x, w1, w2, wd,
                                                         b1, b2, bd);

    dim3 gup(DHID / 128, B_ROWS / 128);    // (16, 256)
    up_gemm_kernel<<<gup, 512, UP_SMEM>>>();

    dim3 gdn(DOUT / 64, B_ROWS / 128);     // (16, 256)
    down_gemm_kernel<<<gdn, 256, DN_SMEM>>>(out);
}